// round 3
// baseline (speedup 1.0000x reference)
#include <cuda_runtime.h>
#include <cuda_bf16.h>
#include <stdint.h>

#define NROWS 8192
#define KDIM  2048
#define NOUT  2048

// Quantized scratch (static device globals: allowed; no runtime allocation)
__device__ __align__(256) uint16_t g_xq[(size_t)NROWS * KDIM]; // bf16 bits
__device__ __align__(256) uint16_t g_wq[(size_t)NOUT * KDIM];  // bf16 bits
__device__ __align__(256) float    g_bq[NOUT];

// ---------------------------------------------------------------------------
// posit(8,1) round-to-nearest quantization (matches the jnp reference).
// ---------------------------------------------------------------------------
__device__ __forceinline__ float posit_q(float x) {
    float ax = fabsf(x);
    if (!(ax > 0.0f)) return 0.0f;                       // x == 0 -> 0
    ax = fminf(fmaxf(ax, 2.44140625e-4f), 4096.0f);      // [2^-12, 2^12]
    int bits = __float_as_int(ax);
    int s = ((bits >> 23) & 0xFF) - 127;                 // floor(log2(ax))
    int k = s >> 1;                                      // floor(s/2), es=1
    int rlen = (k >= 0) ? (k + 2) : (1 - k);
    int fb = 6 - rlen; fb = fb < 0 ? 0 : fb;             // fraction bits
    float m   = __int_as_float((bits & 0x7FFFFF) | 0x3F800000); // [1,2)
    float fs  = __int_as_float((127 + fb) << 23);        // 2^fb
    float inv = __int_as_float((127 - fb) << 23);        // 2^-fb
    float mq = rintf(m * fs) * inv;                      // half-to-even
    if (mq >= 2.0f) { s += 1; mq = 1.0f; }               // carry
    float y = mq * __int_as_float((127 + s) << 23);
    return copysignf(y, x);
}

__device__ __forceinline__ uint32_t pq2(float a, float b) {
    __nv_bfloat162 t = __floats2bfloat162_rn(posit_q(a), posit_q(b)); // exact
    return *reinterpret_cast<uint32_t*>(&t);
}

__global__ void quant4_kernel(const float* __restrict__ src,
                              uint2* __restrict__ dst, int n4) {
    int i = blockIdx.x * blockDim.x + threadIdx.x;
    if (i < n4) {
        float4 v = reinterpret_cast<const float4*>(src)[i];
        uint2 o;
        o.x = pq2(v.x, v.y);
        o.y = pq2(v.z, v.w);
        dst[i] = o;
    }
}

__global__ void quantb_kernel(const float* __restrict__ src,
                              float* __restrict__ dst, int n) {
    int i = blockIdx.x * blockDim.x + threadIdx.x;
    if (i < n) dst[i] = posit_q(src[i]);
}

// ---------------------------------------------------------------------------
// bf16 GEMM via mma.sync (base sm_103 PTX; no tcgen05 available here):
//   out[M,N] = xq @ wq^T + bq ;  M=8192, N=2048, K=2048
// Tile: BM=128 x BN=256, BK=64, 4-stage cp.async, 8 warps of 64x64.
// ---------------------------------------------------------------------------
#define BM 128
#define BN 256
#define BK 64
#define STAGES 4
#define KITERS (KDIM / BK)                 // 32
#define A_BYTES (BM * 128)                 // 16 KB  (BK*2 = 128 B/row)
#define B_BYTES (BN * 128)                 // 32 KB
#define STAGE_BYTES (A_BYTES + B_BYTES)    // 48 KB
#define SMEM_DYN (STAGES * STAGE_BYTES + 1024)

// SW128: 16B chunk c within a 128B row r -> chunk c ^ (r & 7)
__device__ __forceinline__ uint32_t swz(uint32_t row, uint32_t byte) {
    return row * 128u + (byte ^ ((row & 7u) * 16u));
}

__device__ __forceinline__ uint32_t smem_u32(const void* p) {
    uint32_t a;
    asm("{ .reg .u64 t; cvta.to.shared.u64 t, %1; cvt.u32.u64 %0, t; }"
        : "=r"(a) : "l"(p));
    return a;
}

__device__ __forceinline__ void cp16(uint32_t dst, const void* src) {
    asm volatile("cp.async.cg.shared.global [%0], [%1], 16;"
                 :: "r"(dst), "l"(src) : "memory");
}

__device__ __forceinline__ void ldsm4(uint32_t& r0, uint32_t& r1,
                                      uint32_t& r2, uint32_t& r3, uint32_t a) {
    asm volatile("ldmatrix.sync.aligned.m8n8.x4.shared.b16 {%0,%1,%2,%3}, [%4];"
                 : "=r"(r0), "=r"(r1), "=r"(r2), "=r"(r3) : "r"(a));
}

__device__ __forceinline__ void mma16816(float* d, const uint32_t* a,
                                         uint32_t b0, uint32_t b1) {
    asm volatile(
        "mma.sync.aligned.m16n8k16.row.col.f32.bf16.bf16.f32 "
        "{%0,%1,%2,%3}, {%4,%5,%6,%7}, {%8,%9}, {%0,%1,%2,%3};"
        : "+f"(d[0]), "+f"(d[1]), "+f"(d[2]), "+f"(d[3])
        : "r"(a[0]), "r"(a[1]), "r"(a[2]), "r"(a[3]), "r"(b0), "r"(b1));
}

__global__ void __launch_bounds__(256, 1)
gemm_kernel(float* __restrict__ out) {
    extern __shared__ char smem_raw[];
    uint32_t sb = smem_u32(smem_raw);
    sb = (sb + 1023u) & ~1023u;

    const int tid  = threadIdx.x;
    const int wid  = tid >> 5, lane = tid & 31;
    const int wm   = wid & 1;        // 2 warps along M (64 each)
    const int wn   = wid >> 1;       // 4 warps along N (64 each)
    const int n0   = blockIdx.x * BN;
    const int m0   = blockIdx.y * BM;

    // gmem source pointers (bf16 rows, 4096 B/row)
    const char* agp = (const char*)g_xq + (size_t)(m0 + (tid >> 1)) * KDIM * 2
                      + (tid & 1) * 64;
    const char* bgp = (const char*)g_wq + (size_t)(n0 + tid) * KDIM * 2;

    auto load_stage = [&](int s, int it) {
        const uint32_t ab = sb + s * STAGE_BYTES;
        const uint32_t bb = ab + A_BYTES;
        const int koff = it * 128;                       // BK*2 bytes
        const uint32_t ar = tid >> 1;                    // A row (2 thr/row)
        const uint32_t ac0 = (tid & 1) * 64;             // byte offset in row
        #pragma unroll
        for (int c = 0; c < 4; c++)
            cp16(ab + swz(ar, ac0 + c * 16), agp + koff + c * 16);
        #pragma unroll
        for (int c = 0; c < 8; c++)
            cp16(bb + swz(tid, c * 16), bgp + koff + c * 16);
    };

    // Prologue: fill STAGES-1 stages
    #pragma unroll
    for (int s = 0; s < STAGES - 1; s++) {
        load_stage(s, s);
        asm volatile("cp.async.commit_group;" ::: "memory");
    }

    float acc[4][8][4];
    #pragma unroll
    for (int i = 0; i < 4; i++)
        #pragma unroll
        for (int j = 0; j < 8; j++)
            #pragma unroll
            for (int v = 0; v < 4; v++) acc[i][j][v] = 0.0f;

    const uint32_t a_row_lm = wm * 64 + (lane & 15);     // + mt*16
    const uint32_t a_byte_lm = (lane >> 4) * 16;         // + kk*32
    const uint32_t b_row_lm = wn * 64 + ((lane >> 4) * 8) + (lane & 7); // +p*16
    const uint32_t b_byte_lm = ((lane >> 3) & 1) * 16;   // + kk*32

    for (int it = 0; it < KITERS; ++it) {
        if (it + STAGES - 1 < KITERS)
            load_stage((it + STAGES - 1) & (STAGES - 1), it + STAGES - 1);
        asm volatile("cp.async.commit_group;" ::: "memory");
        asm volatile("cp.async.wait_group %0;" :: "n"(STAGES - 2) : "memory");
        __syncthreads();

        const uint32_t ab = sb + (it & (STAGES - 1)) * STAGE_BYTES;
        const uint32_t bb = ab + A_BYTES;

        #pragma unroll
        for (int kk = 0; kk < 4; kk++) {                 // 4 x k16 per stage
            uint32_t af[4][4];
            #pragma unroll
            for (int mt = 0; mt < 4; mt++)
                ldsm4(af[mt][0], af[mt][1], af[mt][2], af[mt][3],
                      ab + swz(a_row_lm + mt * 16, kk * 32 + a_byte_lm));
            uint32_t bf[4][4];                           // [pair]{b0,b1,b0',b1'}
            #pragma unroll
            for (int p = 0; p < 4; p++)
                ldsm4(bf[p][0], bf[p][1], bf[p][2], bf[p][3],
                      bb + swz(b_row_lm + p * 16, kk * 32 + b_byte_lm));
            #pragma unroll
            for (int mt = 0; mt < 4; mt++)
                #pragma unroll
                for (int p = 0; p < 4; p++) {
                    mma16816(acc[mt][2 * p],     af[mt], bf[p][0], bf[p][1]);
                    mma16816(acc[mt][2 * p + 1], af[mt], bf[p][2], bf[p][3]);
                }
        }
        __syncthreads();   // all warps done with this stage before overwrite
    }

    // Epilogue: direct stores + bias (pairs of floats per thread)
    const int ncol = n0 + wn * 64 + (lane & 3) * 2;
    float2 bv[8];
    #pragma unroll
    for (int nt = 0; nt < 8; nt++)
        bv[nt] = *reinterpret_cast<const float2*>(&g_bq[ncol + nt * 8]);

    const int mrow = m0 + wm * 64 + (lane >> 2);
    #pragma unroll
    for (int mt = 0; mt < 4; mt++) {
        float* r0 = out + (size_t)(mrow + mt * 16) * NOUT;
        float* r1 = r0 + 8 * NOUT;
        #pragma unroll
        for (int nt = 0; nt < 8; nt++) {
            float2 lo = make_float2(acc[mt][nt][0] + bv[nt].x,
                                    acc[mt][nt][1] + bv[nt].y);
            float2 hi = make_float2(acc[mt][nt][2] + bv[nt].x,
                                    acc[mt][nt][3] + bv[nt].y);
            *reinterpret_cast<float2*>(r0 + ncol + nt * 8) = lo;
            *reinterpret_cast<float2*>(r1 + ncol + nt * 8) = hi;
        }
    }
}

// ---------------------------------------------------------------------------
extern "C" void kernel_launch(void* const* d_in, const int* in_sizes, int n_in,
                              void* d_out, int out_size) {
    const float* x = nullptr; const float* w = nullptr; const float* b = nullptr;
    for (int i = 0; i < n_in; i++) {
        if (in_sizes[i] == NROWS * KDIM)      x = (const float*)d_in[i];
        else if (in_sizes[i] == NOUT * KDIM)  w = (const float*)d_in[i];
        else if (in_sizes[i] == NOUT)         b = (const float*)d_in[i];
    }

    void* xq_p; cudaGetSymbolAddress(&xq_p, g_xq);
    void* wq_p; cudaGetSymbolAddress(&wq_p, g_wq);
    void* bq_p; cudaGetSymbolAddress(&bq_p, g_bq);

    {
        int n4 = (NROWS * KDIM) / 4;
        quant4_kernel<<<(n4 + 255) / 256, 256>>>(x, (uint2*)xq_p, n4);
    }
    {
        int n4 = (NOUT * KDIM) / 4;
        quant4_kernel<<<(n4 + 255) / 256, 256>>>(w, (uint2*)wq_p, n4);
    }
    quantb_kernel<<<(NOUT + 255) / 256, 256>>>(b, (float*)bq_p, NOUT);

    cudaFuncSetAttribute(gemm_kernel,
                         cudaFuncAttributeMaxDynamicSharedMemorySize, SMEM_DYN);
    dim3 grid(NOUT / BN, NROWS / BM);   // (8, 64)
    gemm_kernel<<<grid, 256, SMEM_DYN>>>((float*)d_out);
}

// round 4
// speedup vs baseline: 1.3310x; 1.3310x over previous
#include <cuda_runtime.h>
#include <cuda_bf16.h>
#include <stdint.h>

#define NROWS 8192
#define KDIM  2048
#define NOUT  2048

__device__ __align__(256) uint16_t g_xq[(size_t)NROWS * KDIM]; // bf16 bits
__device__ __align__(256) uint16_t g_wq[(size_t)NOUT * KDIM];  // bf16 bits
__device__ __align__(256) float    g_bq[NOUT];

// ---------------------------------------------------------------------------
// posit(8,1) round-to-nearest quantization (matches the jnp reference).
// ---------------------------------------------------------------------------
__device__ __forceinline__ float posit_q(float x) {
    float ax = fabsf(x);
    if (!(ax > 0.0f)) return 0.0f;
    ax = fminf(fmaxf(ax, 2.44140625e-4f), 4096.0f);      // [2^-12, 2^12]
    int bits = __float_as_int(ax);
    int s = ((bits >> 23) & 0xFF) - 127;
    int k = s >> 1;
    int rlen = (k >= 0) ? (k + 2) : (1 - k);
    int fb = 6 - rlen; fb = fb < 0 ? 0 : fb;
    float m   = __int_as_float((bits & 0x7FFFFF) | 0x3F800000);
    float fs  = __int_as_float((127 + fb) << 23);
    float inv = __int_as_float((127 - fb) << 23);
    float mq = rintf(m * fs) * inv;
    if (mq >= 2.0f) { s += 1; mq = 1.0f; }
    float y = mq * __int_as_float((127 + s) << 23);
    return copysignf(y, x);
}

__device__ __forceinline__ uint32_t pq2(float a, float b) {
    __nv_bfloat162 t = __floats2bfloat162_rn(posit_q(a), posit_q(b));
    return *reinterpret_cast<uint32_t*>(&t);
}

__global__ void quant4_kernel(const float* __restrict__ src,
                              uint2* __restrict__ dst, int n4) {
    int i = blockIdx.x * blockDim.x + threadIdx.x;
    if (i < n4) {
        float4 v = reinterpret_cast<const float4*>(src)[i];
        uint2 o;
        o.x = pq2(v.x, v.y);
        o.y = pq2(v.z, v.w);
        dst[i] = o;
    }
}

__global__ void quantb_kernel(const float* __restrict__ src,
                              float* __restrict__ dst, int n) {
    int i = blockIdx.x * blockDim.x + threadIdx.x;
    if (i < n) dst[i] = posit_q(src[i]);
}

// ---------------------------------------------------------------------------
// bf16 mma.sync GEMM: out = xq @ wq^T + bq  (M=8192, N=2048, K=2048)
// BM=128 x BN=256, BK=64, STAGES=4 cp.async, 512 threads (16 warps, 2x8),
// warp tile 64x32, single __syncthreads per mainloop iteration.
// ---------------------------------------------------------------------------
#define BM 128
#define BN 256
#define BK 64
#define STAGES 4
#define KITERS (KDIM / BK)                 // 32
#define A_BYTES (BM * 128)                 // 16 KB
#define B_BYTES (BN * 128)                 // 32 KB
#define STAGE_BYTES (A_BYTES + B_BYTES)    // 48 KB
#define SMEM_DYN (STAGES * STAGE_BYTES + 1024)

__device__ __forceinline__ uint32_t swz(uint32_t row, uint32_t byte) {
    return row * 128u + (byte ^ ((row & 7u) * 16u));
}

__device__ __forceinline__ uint32_t smem_u32(const void* p) {
    uint32_t a;
    asm("{ .reg .u64 t; cvta.to.shared.u64 t, %1; cvt.u32.u64 %0, t; }"
        : "=r"(a) : "l"(p));
    return a;
}

__device__ __forceinline__ void cp16(uint32_t dst, const void* src) {
    asm volatile("cp.async.cg.shared.global [%0], [%1], 16;"
                 :: "r"(dst), "l"(src) : "memory");
}

__device__ __forceinline__ void ldsm4(uint32_t& r0, uint32_t& r1,
                                      uint32_t& r2, uint32_t& r3, uint32_t a) {
    asm volatile("ldmatrix.sync.aligned.m8n8.x4.shared.b16 {%0,%1,%2,%3}, [%4];"
                 : "=r"(r0), "=r"(r1), "=r"(r2), "=r"(r3) : "r"(a));
}

__device__ __forceinline__ void mma16816(float* d, const uint32_t* a,
                                         uint32_t b0, uint32_t b1) {
    asm volatile(
        "mma.sync.aligned.m16n8k16.row.col.f32.bf16.bf16.f32 "
        "{%0,%1,%2,%3}, {%4,%5,%6,%7}, {%8,%9}, {%0,%1,%2,%3};"
        : "+f"(d[0]), "+f"(d[1]), "+f"(d[2]), "+f"(d[3])
        : "r"(a[0]), "r"(a[1]), "r"(a[2]), "r"(a[3]), "r"(b0), "r"(b1));
}

__global__ void __launch_bounds__(512, 1)
gemm_kernel(float* __restrict__ out) {
    extern __shared__ char smem_raw[];
    uint32_t sb = smem_u32(smem_raw);
    sb = (sb + 1023u) & ~1023u;

    const int tid  = threadIdx.x;
    const int wid  = tid >> 5, lane = tid & 31;
    const int wm   = wid & 1;        // 2 warps along M (64 rows each)
    const int wn   = wid >> 1;       // 8 warps along N (32 cols each)
    const int n0   = blockIdx.x * BN;
    const int m0   = blockIdx.y * BM;

    // gmem pointers: A 4 thr/row (32B each), B 2 thr/row (64B each)
    const char* agp = (const char*)g_xq + (size_t)(m0 + (tid >> 2)) * KDIM * 2
                      + (tid & 3) * 32;
    const char* bgp = (const char*)g_wq + (size_t)(n0 + (tid >> 1)) * KDIM * 2
                      + (tid & 1) * 64;

    auto load_stage = [&](int s, int it) {
        const uint32_t ab = sb + s * STAGE_BYTES;
        const uint32_t bb = ab + A_BYTES;
        const int koff = it * 128;                       // BK*2 bytes
        const uint32_t ar  = tid >> 2;
        const uint32_t ac0 = (tid & 3) * 32;
        #pragma unroll
        for (int c = 0; c < 2; c++)
            cp16(ab + swz(ar, ac0 + c * 16), agp + koff + c * 16);
        const uint32_t br  = tid >> 1;
        const uint32_t bc0 = (tid & 1) * 64;
        #pragma unroll
        for (int c = 0; c < 4; c++)
            cp16(bb + swz(br, bc0 + c * 16), bgp + koff + c * 16);
    };

    #pragma unroll
    for (int s = 0; s < STAGES - 1; s++) {
        load_stage(s, s);
        asm volatile("cp.async.commit_group;" ::: "memory");
    }

    float acc[4][4][4];
    #pragma unroll
    for (int i = 0; i < 4; i++)
        #pragma unroll
        for (int j = 0; j < 4; j++)
            #pragma unroll
            for (int v = 0; v < 4; v++) acc[i][j][v] = 0.0f;

    const uint32_t a_row_lm  = wm * 64 + (lane & 15);         // + mt*16
    const uint32_t a_byte_lm = (lane >> 4) * 16;              // + kk*32
    const uint32_t b_row_lm  = wn * 32 + ((lane >> 4) * 8) + (lane & 7); // +p*16
    const uint32_t b_byte_lm = ((lane >> 3) & 1) * 16;        // + kk*32

    for (int it = 0; it < KITERS; ++it) {
        asm volatile("cp.async.wait_group %0;" :: "n"(STAGES - 2) : "memory");
        __syncthreads();
        if (it + STAGES - 1 < KITERS)
            load_stage((it + STAGES - 1) & (STAGES - 1), it + STAGES - 1);
        asm volatile("cp.async.commit_group;" ::: "memory");

        const uint32_t ab = sb + (it & (STAGES - 1)) * STAGE_BYTES;
        const uint32_t bb = ab + A_BYTES;

        #pragma unroll
        for (int kk = 0; kk < 4; kk++) {                 // 4 x k16 per stage
            uint32_t af[4][4];
            #pragma unroll
            for (int mt = 0; mt < 4; mt++)
                ldsm4(af[mt][0], af[mt][1], af[mt][2], af[mt][3],
                      ab + swz(a_row_lm + mt * 16, kk * 32 + a_byte_lm));
            uint32_t bf[2][4];
            #pragma unroll
            for (int p = 0; p < 2; p++)
                ldsm4(bf[p][0], bf[p][1], bf[p][2], bf[p][3],
                      bb + swz(b_row_lm + p * 16, kk * 32 + b_byte_lm));
            #pragma unroll
            for (int mt = 0; mt < 4; mt++)
                #pragma unroll
                for (int p = 0; p < 2; p++) {
                    mma16816(acc[mt][2 * p],     af[mt], bf[p][0], bf[p][1]);
                    mma16816(acc[mt][2 * p + 1], af[mt], bf[p][2], bf[p][3]);
                }
        }
    }

    // Epilogue: direct float2 stores + bias
    const int ncol = n0 + wn * 32 + (lane & 3) * 2;
    float2 bv[4];
    #pragma unroll
    for (int nt = 0; nt < 4; nt++)
        bv[nt] = *reinterpret_cast<const float2*>(&g_bq[ncol + nt * 8]);

    const int mrow = m0 + wm * 64 + (lane >> 2);
    #pragma unroll
    for (int mt = 0; mt < 4; mt++) {
        float* r0 = out + (size_t)(mrow + mt * 16) * NOUT;
        float* r1 = r0 + 8 * NOUT;
        #pragma unroll
        for (int nt = 0; nt < 4; nt++) {
            float2 lo = make_float2(acc[mt][nt][0] + bv[nt].x,
                                    acc[mt][nt][1] + bv[nt].y);
            float2 hi = make_float2(acc[mt][nt][2] + bv[nt].x,
                                    acc[mt][nt][3] + bv[nt].y);
            *reinterpret_cast<float2*>(r0 + ncol + nt * 8) = lo;
            *reinterpret_cast<float2*>(r1 + ncol + nt * 8) = hi;
        }
    }
}

// ---------------------------------------------------------------------------
extern "C" void kernel_launch(void* const* d_in, const int* in_sizes, int n_in,
                              void* d_out, int out_size) {
    const float* x = nullptr; const float* w = nullptr; const float* b = nullptr;
    for (int i = 0; i < n_in; i++) {
        if (in_sizes[i] == NROWS * KDIM)      x = (const float*)d_in[i];
        else if (in_sizes[i] == NOUT * KDIM)  w = (const float*)d_in[i];
        else if (in_sizes[i] == NOUT)         b = (const float*)d_in[i];
    }

    void* xq_p; cudaGetSymbolAddress(&xq_p, g_xq);
    void* wq_p; cudaGetSymbolAddress(&wq_p, g_wq);
    void* bq_p; cudaGetSymbolAddress(&bq_p, g_bq);

    {
        int n4 = (NROWS * KDIM) / 4;
        quant4_kernel<<<(n4 + 255) / 256, 256>>>(x, (uint2*)xq_p, n4);
    }
    {
        int n4 = (NOUT * KDIM) / 4;
        quant4_kernel<<<(n4 + 255) / 256, 256>>>(w, (uint2*)wq_p, n4);
    }
    quantb_kernel<<<(NOUT + 255) / 256, 256>>>(b, (float*)bq_p, NOUT);

    cudaFuncSetAttribute(gemm_kernel,
                         cudaFuncAttributeMaxDynamicSharedMemorySize, SMEM_DYN);
    dim3 grid(NOUT / BN, NROWS / BM);   // (8, 64)
    gemm_kernel<<<grid, 512, SMEM_DYN>>>((float*)d_out);
}

// round 5
// speedup vs baseline: 1.3332x; 1.0016x over previous
#include <cuda_runtime.h>
#include <cuda_bf16.h>
#include <stdint.h>

#define NROWS 8192
#define KDIM  2048
#define NOUT  2048

__device__ __align__(256) uint16_t g_xq[(size_t)NROWS * KDIM]; // bf16 bits
__device__ __align__(256) uint16_t g_wq[(size_t)NOUT * KDIM];  // bf16 bits
__device__ __align__(256) float    g_bq[NOUT];

// ---------------------------------------------------------------------------
// posit(8,1) round-to-nearest quantization (matches the jnp reference).
// ---------------------------------------------------------------------------
__device__ __forceinline__ float posit_q(float x) {
    float ax = fabsf(x);
    if (!(ax > 0.0f)) return 0.0f;
    ax = fminf(fmaxf(ax, 2.44140625e-4f), 4096.0f);      // [2^-12, 2^12]
    int bits = __float_as_int(ax);
    int s = ((bits >> 23) & 0xFF) - 127;
    int k = s >> 1;
    int rlen = (k >= 0) ? (k + 2) : (1 - k);
    int fb = 6 - rlen; fb = fb < 0 ? 0 : fb;
    float m   = __int_as_float((bits & 0x7FFFFF) | 0x3F800000);
    float fs  = __int_as_float((127 + fb) << 23);
    float inv = __int_as_float((127 - fb) << 23);
    float mq = rintf(m * fs) * inv;
    if (mq >= 2.0f) { s += 1; mq = 1.0f; }
    float y = mq * __int_as_float((127 + s) << 23);
    return copysignf(y, x);
}

__device__ __forceinline__ uint32_t pq2(float a, float b) {
    __nv_bfloat162 t = __floats2bfloat162_rn(posit_q(a), posit_q(b));
    return *reinterpret_cast<uint32_t*>(&t);
}

__global__ void quant4_kernel(const float* __restrict__ src,
                              uint2* __restrict__ dst, int n4) {
    int i = blockIdx.x * blockDim.x + threadIdx.x;
    if (i < n4) {
        float4 v = reinterpret_cast<const float4*>(src)[i];
        uint2 o;
        o.x = pq2(v.x, v.y);
        o.y = pq2(v.z, v.w);
        dst[i] = o;
    }
}

__global__ void quantb_kernel(const float* __restrict__ src,
                              float* __restrict__ dst, int n) {
    int i = blockIdx.x * blockDim.x + threadIdx.x;
    if (i < n) dst[i] = posit_q(src[i]);
}

// ---------------------------------------------------------------------------
// bf16 mma.sync GEMM: out = xq @ wq^T + bq  (M=8192, N=2048, K=2048)
// BM=128 x BN=256, BK=64, STAGES=4 cp.async, 1024 threads (32 warps, 4x8),
// warp tile 32x32 (acc 32 regs), <=64 regs/thread -> 32 warps resident.
// ---------------------------------------------------------------------------
#define BM 128
#define BN 256
#define BK 64
#define STAGES 4
#define KITERS (KDIM / BK)                 // 32
#define A_BYTES (BM * 128)                 // 16 KB
#define B_BYTES (BN * 128)                 // 32 KB
#define STAGE_BYTES (A_BYTES + B_BYTES)    // 48 KB
#define SMEM_DYN (STAGES * STAGE_BYTES + 1024)

__device__ __forceinline__ uint32_t swz(uint32_t row, uint32_t byte) {
    return row * 128u + (byte ^ ((row & 7u) * 16u));
}

__device__ __forceinline__ uint32_t smem_u32(const void* p) {
    uint32_t a;
    asm("{ .reg .u64 t; cvta.to.shared.u64 t, %1; cvt.u32.u64 %0, t; }"
        : "=r"(a) : "l"(p));
    return a;
}

__device__ __forceinline__ void cp16(uint32_t dst, const void* src) {
    asm volatile("cp.async.cg.shared.global [%0], [%1], 16;"
                 :: "r"(dst), "l"(src) : "memory");
}

__device__ __forceinline__ void ldsm4(uint32_t& r0, uint32_t& r1,
                                      uint32_t& r2, uint32_t& r3, uint32_t a) {
    asm volatile("ldmatrix.sync.aligned.m8n8.x4.shared.b16 {%0,%1,%2,%3}, [%4];"
                 : "=r"(r0), "=r"(r1), "=r"(r2), "=r"(r3) : "r"(a));
}

__device__ __forceinline__ void mma16816(float* d, const uint32_t* a,
                                         uint32_t b0, uint32_t b1) {
    asm volatile(
        "mma.sync.aligned.m16n8k16.row.col.f32.bf16.bf16.f32 "
        "{%0,%1,%2,%3}, {%4,%5,%6,%7}, {%8,%9}, {%0,%1,%2,%3};"
        : "+f"(d[0]), "+f"(d[1]), "+f"(d[2]), "+f"(d[3])
        : "r"(a[0]), "r"(a[1]), "r"(a[2]), "r"(a[3]), "r"(b0), "r"(b1));
}

__global__ void __launch_bounds__(1024, 1)
gemm_kernel(float* __restrict__ out) {
    extern __shared__ char smem_raw[];
    uint32_t sb = smem_u32(smem_raw);
    sb = (sb + 1023u) & ~1023u;

    const int tid  = threadIdx.x;
    const int wid  = tid >> 5, lane = tid & 31;
    const int wm   = wid & 3;        // 4 warps along M (32 rows each)
    const int wn   = wid >> 2;       // 8 warps along N (32 cols each)
    const int n0   = blockIdx.x * BN;
    const int m0   = blockIdx.y * BM;

    // gmem pointers: A 8 thr/row (16B each), B 4 thr/row (32B each)
    const char* agp = (const char*)g_xq + (size_t)(m0 + (tid >> 3)) * KDIM * 2
                      + (tid & 7) * 16;
    const char* bgp = (const char*)g_wq + (size_t)(n0 + (tid >> 2)) * KDIM * 2
                      + (tid & 3) * 32;

    auto load_stage = [&](int s, int it) {
        const uint32_t ab = sb + s * STAGE_BYTES;
        const uint32_t bb = ab + A_BYTES;
        const int koff = it * 128;                       // BK*2 bytes
        cp16(ab + swz(tid >> 3, (tid & 7) * 16), agp + koff);
        const uint32_t br  = tid >> 2;
        const uint32_t bc0 = (tid & 3) * 32;
        cp16(bb + swz(br, bc0),      bgp + koff);
        cp16(bb + swz(br, bc0 + 16), bgp + koff + 16);
    };

    #pragma unroll
    for (int s = 0; s < STAGES - 1; s++) {
        load_stage(s, s);
        asm volatile("cp.async.commit_group;" ::: "memory");
    }

    float acc[2][4][4];
    #pragma unroll
    for (int i = 0; i < 2; i++)
        #pragma unroll
        for (int j = 0; j < 4; j++)
            #pragma unroll
            for (int v = 0; v < 4; v++) acc[i][j][v] = 0.0f;

    const uint32_t a_row_lm  = wm * 32 + (lane & 15);         // + mt*16
    const uint32_t a_byte_lm = (lane >> 4) * 16;              // + kk*32
    const uint32_t b_row_lm  = wn * 32 + ((lane >> 4) * 8) + (lane & 7); // +p*16
    const uint32_t b_byte_lm = ((lane >> 3) & 1) * 16;        // + kk*32

    for (int it = 0; it < KITERS; ++it) {
        asm volatile("cp.async.wait_group %0;" :: "n"(STAGES - 2) : "memory");
        __syncthreads();
        if (it + STAGES - 1 < KITERS)
            load_stage((it + STAGES - 1) & (STAGES - 1), it + STAGES - 1);
        asm volatile("cp.async.commit_group;" ::: "memory");

        const uint32_t ab = sb + (it & (STAGES - 1)) * STAGE_BYTES;
        const uint32_t bb = ab + A_BYTES;

        #pragma unroll
        for (int kk = 0; kk < 4; kk++) {                 // 4 x k16 per stage
            uint32_t af[2][4];
            #pragma unroll
            for (int mt = 0; mt < 2; mt++)
                ldsm4(af[mt][0], af[mt][1], af[mt][2], af[mt][3],
                      ab + swz(a_row_lm + mt * 16, kk * 32 + a_byte_lm));
            uint32_t bf[2][4];
            #pragma unroll
            for (int p = 0; p < 2; p++)
                ldsm4(bf[p][0], bf[p][1], bf[p][2], bf[p][3],
                      bb + swz(b_row_lm + p * 16, kk * 32 + b_byte_lm));
            #pragma unroll
            for (int mt = 0; mt < 2; mt++)
                #pragma unroll
                for (int p = 0; p < 2; p++) {
                    mma16816(acc[mt][2 * p],     af[mt], bf[p][0], bf[p][1]);
                    mma16816(acc[mt][2 * p + 1], af[mt], bf[p][2], bf[p][3]);
                }
        }
    }

    // Epilogue: direct float2 stores + bias
    const int ncol = n0 + wn * 32 + (lane & 3) * 2;
    float2 bv[4];
    #pragma unroll
    for (int nt = 0; nt < 4; nt++)
        bv[nt] = *reinterpret_cast<const float2*>(&g_bq[ncol + nt * 8]);

    const int mrow = m0 + wm * 32 + (lane >> 2);
    #pragma unroll
    for (int mt = 0; mt < 2; mt++) {
        float* r0 = out + (size_t)(mrow + mt * 16) * NOUT;
        float* r1 = r0 + 8 * NOUT;
        #pragma unroll
        for (int nt = 0; nt < 4; nt++) {
            float2 lo = make_float2(acc[mt][nt][0] + bv[nt].x,
                                    acc[mt][nt][1] + bv[nt].y);
            float2 hi = make_float2(acc[mt][nt][2] + bv[nt].x,
                                    acc[mt][nt][3] + bv[nt].y);
            *reinterpret_cast<float2*>(r0 + ncol + nt * 8) = lo;
            *reinterpret_cast<float2*>(r1 + ncol + nt * 8) = hi;
        }
    }
}

// ---------------------------------------------------------------------------
extern "C" void kernel_launch(void* const* d_in, const int* in_sizes, int n_in,
                              void* d_out, int out_size) {
    const float* x = nullptr; const float* w = nullptr; const float* b = nullptr;
    for (int i = 0; i < n_in; i++) {
        if (in_sizes[i] == NROWS * KDIM)      x = (const float*)d_in[i];
        else if (in_sizes[i] == NOUT * KDIM)  w = (const float*)d_in[i];
        else if (in_sizes[i] == NOUT)         b = (const float*)d_in[i];
    }

    void* xq_p; cudaGetSymbolAddress(&xq_p, g_xq);
    void* wq_p; cudaGetSymbolAddress(&wq_p, g_wq);
    void* bq_p; cudaGetSymbolAddress(&bq_p, g_bq);

    {
        int n4 = (NROWS * KDIM) / 4;
        quant4_kernel<<<(n4 + 255) / 256, 256>>>(x, (uint2*)xq_p, n4);
    }
    {
        int n4 = (NOUT * KDIM) / 4;
        quant4_kernel<<<(n4 + 255) / 256, 256>>>(w, (uint2*)wq_p, n4);
    }
    quantb_kernel<<<(NOUT + 255) / 256, 256>>>(b, (float*)bq_p, NOUT);

    cudaFuncSetAttribute(gemm_kernel,
                         cudaFuncAttributeMaxDynamicSharedMemorySize, SMEM_DYN);
    dim3 grid(NOUT / BN, NROWS / BM);   // (8, 64)
    gemm_kernel<<<grid, 1024, SMEM_DYN>>>((float*)d_out);
}

// round 6
// speedup vs baseline: 1.4301x; 1.0727x over previous
#include <cuda_runtime.h>
#include <cuda_bf16.h>
#include <stdint.h>

#define NROWS 8192
#define KDIM  2048
#define NOUT  2048

__device__ __align__(256) uint16_t g_xq[(size_t)NROWS * KDIM]; // bf16 bits
__device__ __align__(256) uint16_t g_wq[(size_t)NOUT * KDIM];  // bf16 bits
__device__ __align__(256) float    g_bq[NOUT];

// ---------------------------------------------------------------------------
// posit(8,1) round-to-nearest quantization (matches the jnp reference).
// ---------------------------------------------------------------------------
__device__ __forceinline__ float posit_q(float x) {
    float ax = fabsf(x);
    if (!(ax > 0.0f)) return 0.0f;
    ax = fminf(fmaxf(ax, 2.44140625e-4f), 4096.0f);      // [2^-12, 2^12]
    int bits = __float_as_int(ax);
    int s = ((bits >> 23) & 0xFF) - 127;
    int k = s >> 1;
    int rlen = (k >= 0) ? (k + 2) : (1 - k);
    int fb = 6 - rlen; fb = fb < 0 ? 0 : fb;
    float m   = __int_as_float((bits & 0x7FFFFF) | 0x3F800000);
    float fs  = __int_as_float((127 + fb) << 23);
    float inv = __int_as_float((127 - fb) << 23);
    float mq = rintf(m * fs) * inv;
    if (mq >= 2.0f) { s += 1; mq = 1.0f; }
    float y = mq * __int_as_float((127 + s) << 23);
    return copysignf(y, x);
}

__device__ __forceinline__ uint32_t pq2(float a, float b) {
    __nv_bfloat162 t = __floats2bfloat162_rn(posit_q(a), posit_q(b));
    return *reinterpret_cast<uint32_t*>(&t);
}

__global__ void quant4_kernel(const float* __restrict__ src,
                              uint2* __restrict__ dst, int n4) {
    int i = blockIdx.x * blockDim.x + threadIdx.x;
    if (i < n4) {
        float4 v = reinterpret_cast<const float4*>(src)[i];
        uint2 o;
        o.x = pq2(v.x, v.y);
        o.y = pq2(v.z, v.w);
        dst[i] = o;
    }
}

__global__ void quantb_kernel(const float* __restrict__ src,
                              float* __restrict__ dst, int n) {
    int i = blockIdx.x * blockDim.x + threadIdx.x;
    if (i < n) dst[i] = posit_q(src[i]);
}

// ---------------------------------------------------------------------------
// bf16 mma.sync GEMM: out = xq @ wq^T + bq  (M=8192, N=2048, K=2048)
// BM=128 x BN=128, BK=64, STAGES=3, 256 threads (8 warps, 2x4),
// warp tile 64x32, 2 CTAs per SM (barrier decoupling + lower smem B/MMA).
// ---------------------------------------------------------------------------
#define BM 128
#define BN 128
#define BK 64
#define STAGES 3
#define KITERS (KDIM / BK)                 // 32
#define A_BYTES (BM * 128)                 // 16 KB
#define B_BYTES (BN * 128)                 // 16 KB
#define STAGE_BYTES (A_BYTES + B_BYTES)    // 32 KB
#define SMEM_DYN (STAGES * STAGE_BYTES + 1024)

__device__ __forceinline__ uint32_t swz(uint32_t row, uint32_t byte) {
    return row * 128u + (byte ^ ((row & 7u) * 16u));
}

__device__ __forceinline__ uint32_t smem_u32(const void* p) {
    uint32_t a;
    asm("{ .reg .u64 t; cvta.to.shared.u64 t, %1; cvt.u32.u64 %0, t; }"
        : "=r"(a) : "l"(p));
    return a;
}

__device__ __forceinline__ void cp16(uint32_t dst, const void* src) {
    asm volatile("cp.async.cg.shared.global [%0], [%1], 16;"
                 :: "r"(dst), "l"(src) : "memory");
}

__device__ __forceinline__ void ldsm4(uint32_t& r0, uint32_t& r1,
                                      uint32_t& r2, uint32_t& r3, uint32_t a) {
    asm volatile("ldmatrix.sync.aligned.m8n8.x4.shared.b16 {%0,%1,%2,%3}, [%4];"
                 : "=r"(r0), "=r"(r1), "=r"(r2), "=r"(r3) : "r"(a));
}

__device__ __forceinline__ void mma16816(float* d, const uint32_t* a,
                                         uint32_t b0, uint32_t b1) {
    asm volatile(
        "mma.sync.aligned.m16n8k16.row.col.f32.bf16.bf16.f32 "
        "{%0,%1,%2,%3}, {%4,%5,%6,%7}, {%8,%9}, {%0,%1,%2,%3};"
        : "+f"(d[0]), "+f"(d[1]), "+f"(d[2]), "+f"(d[3])
        : "r"(a[0]), "r"(a[1]), "r"(a[2]), "r"(a[3]), "r"(b0), "r"(b1));
}

__global__ void __launch_bounds__(256, 2)
gemm_kernel(float* __restrict__ out) {
    extern __shared__ char smem_raw[];
    uint32_t sb = smem_u32(smem_raw);
    sb = (sb + 1023u) & ~1023u;

    const int tid  = threadIdx.x;
    const int wid  = tid >> 5, lane = tid & 31;
    const int wm   = wid & 1;        // 2 warps along M (64 rows each)
    const int wn   = wid >> 1;       // 4 warps along N (32 cols each)
    const int n0   = blockIdx.x * BN;
    const int m0   = blockIdx.y * BM;

    // gmem pointers: A and B both 2 thr/row (64B each)
    const char* agp = (const char*)g_xq + (size_t)(m0 + (tid >> 1)) * KDIM * 2
                      + (tid & 1) * 64;
    const char* bgp = (const char*)g_wq + (size_t)(n0 + (tid >> 1)) * KDIM * 2
                      + (tid & 1) * 64;

    auto load_stage = [&](int s, int it) {
        const uint32_t ab = sb + s * STAGE_BYTES;
        const uint32_t bb = ab + A_BYTES;
        const int koff = it * 128;                       // BK*2 bytes
        const uint32_t r  = tid >> 1;
        const uint32_t c0 = (tid & 1) * 64;
        #pragma unroll
        for (int c = 0; c < 4; c++)
            cp16(ab + swz(r, c0 + c * 16), agp + koff + c * 16);
        #pragma unroll
        for (int c = 0; c < 4; c++)
            cp16(bb + swz(r, c0 + c * 16), bgp + koff + c * 16);
    };

    #pragma unroll
    for (int s = 0; s < STAGES - 1; s++) {
        load_stage(s, s);
        asm volatile("cp.async.commit_group;" ::: "memory");
    }

    float acc[4][4][4];
    #pragma unroll
    for (int i = 0; i < 4; i++)
        #pragma unroll
        for (int j = 0; j < 4; j++)
            #pragma unroll
            for (int v = 0; v < 4; v++) acc[i][j][v] = 0.0f;

    const uint32_t a_row_lm  = wm * 64 + (lane & 15);         // + mt*16
    const uint32_t a_byte_lm = (lane >> 4) * 16;              // + kk*32
    const uint32_t b_row_lm  = wn * 32 + ((lane >> 4) * 8) + (lane & 7); // +p*16
    const uint32_t b_byte_lm = ((lane >> 3) & 1) * 16;        // + kk*32

    int s_rd = 0, s_wr = STAGES - 1;
    for (int it = 0; it < KITERS; ++it) {
        asm volatile("cp.async.wait_group %0;" :: "n"(STAGES - 2) : "memory");
        __syncthreads();
        if (it + STAGES - 1 < KITERS)
            load_stage(s_wr, it + STAGES - 1);
        asm volatile("cp.async.commit_group;" ::: "memory");
        if (++s_wr == STAGES) s_wr = 0;

        const uint32_t ab = sb + s_rd * STAGE_BYTES;
        const uint32_t bb = ab + A_BYTES;
        if (++s_rd == STAGES) s_rd = 0;

        #pragma unroll
        for (int kk = 0; kk < 4; kk++) {                 // 4 x k16 per stage
            uint32_t af[4][4];
            #pragma unroll
            for (int mt = 0; mt < 4; mt++)
                ldsm4(af[mt][0], af[mt][1], af[mt][2], af[mt][3],
                      ab + swz(a_row_lm + mt * 16, kk * 32 + a_byte_lm));
            uint32_t bf[2][4];
            #pragma unroll
            for (int p = 0; p < 2; p++)
                ldsm4(bf[p][0], bf[p][1], bf[p][2], bf[p][3],
                      bb + swz(b_row_lm + p * 16, kk * 32 + b_byte_lm));
            #pragma unroll
            for (int mt = 0; mt < 4; mt++)
                #pragma unroll
                for (int p = 0; p < 2; p++) {
                    mma16816(acc[mt][2 * p],     af[mt], bf[p][0], bf[p][1]);
                    mma16816(acc[mt][2 * p + 1], af[mt], bf[p][2], bf[p][3]);
                }
        }
    }

    // Epilogue: direct float2 stores + bias
    const int ncol = n0 + wn * 32 + (lane & 3) * 2;
    float2 bv[4];
    #pragma unroll
    for (int nt = 0; nt < 4; nt++)
        bv[nt] = *reinterpret_cast<const float2*>(&g_bq[ncol + nt * 8]);

    const int mrow = m0 + wm * 64 + (lane >> 2);
    #pragma unroll
    for (int mt = 0; mt < 4; mt++) {
        float* r0 = out + (size_t)(mrow + mt * 16) * NOUT;
        float* r1 = r0 + 8 * NOUT;
        #pragma unroll
        for (int nt = 0; nt < 4; nt++) {
            float2 lo = make_float2(acc[mt][nt][0] + bv[nt].x,
                                    acc[mt][nt][1] + bv[nt].y);
            float2 hi = make_float2(acc[mt][nt][2] + bv[nt].x,
                                    acc[mt][nt][3] + bv[nt].y);
            *reinterpret_cast<float2*>(r0 + ncol + nt * 8) = lo;
            *reinterpret_cast<float2*>(r1 + ncol + nt * 8) = hi;
        }
    }
}

// ---------------------------------------------------------------------------
extern "C" void kernel_launch(void* const* d_in, const int* in_sizes, int n_in,
                              void* d_out, int out_size) {
    const float* x = nullptr; const float* w = nullptr; const float* b = nullptr;
    for (int i = 0; i < n_in; i++) {
        if (in_sizes[i] == NROWS * KDIM)      x = (const float*)d_in[i];
        else if (in_sizes[i] == NOUT * KDIM)  w = (const float*)d_in[i];
        else if (in_sizes[i] == NOUT)         b = (const float*)d_in[i];
    }

    void* xq_p; cudaGetSymbolAddress(&xq_p, g_xq);
    void* wq_p; cudaGetSymbolAddress(&wq_p, g_wq);
    void* bq_p; cudaGetSymbolAddress(&bq_p, g_bq);

    {
        int n4 = (NROWS * KDIM) / 4;
        quant4_kernel<<<(n4 + 255) / 256, 256>>>(x, (uint2*)xq_p, n4);
    }
    {
        int n4 = (NOUT * KDIM) / 4;
        quant4_kernel<<<(n4 + 255) / 256, 256>>>(w, (uint2*)wq_p, n4);
    }
    quantb_kernel<<<(NOUT + 255) / 256, 256>>>(b, (float*)bq_p, NOUT);

    cudaFuncSetAttribute(gemm_kernel,
                         cudaFuncAttributeMaxDynamicSharedMemorySize, SMEM_DYN);
    dim3 grid(NOUT / BN, NROWS / BM);   // (16, 64)
    gemm_kernel<<<grid, 256, SMEM_DYN>>>((float*)d_out);
}

// round 7
// speedup vs baseline: 1.4863x; 1.0393x over previous
#include <cuda_runtime.h>
#include <cuda_bf16.h>
#include <stdint.h>

#define NROWS 8192
#define KDIM  2048
#define NOUT  2048

__device__ __align__(256) uint16_t g_xq[(size_t)NROWS * KDIM]; // bf16 bits
__device__ __align__(256) uint16_t g_wq[(size_t)NOUT * KDIM];  // bf16 bits
__device__ __align__(256) float    g_bq[NOUT];

// ---------------------------------------------------------------------------
// posit(8,1) round-to-nearest quantization (matches the jnp reference).
// ---------------------------------------------------------------------------
__device__ __forceinline__ float posit_q(float x) {
    float ax = fabsf(x);
    if (!(ax > 0.0f)) return 0.0f;
    ax = fminf(fmaxf(ax, 2.44140625e-4f), 4096.0f);      // [2^-12, 2^12]
    int bits = __float_as_int(ax);
    int s = ((bits >> 23) & 0xFF) - 127;
    int k = s >> 1;
    int rlen = (k >= 0) ? (k + 2) : (1 - k);
    int fb = 6 - rlen; fb = fb < 0 ? 0 : fb;
    float m   = __int_as_float((bits & 0x7FFFFF) | 0x3F800000);
    float fs  = __int_as_float((127 + fb) << 23);
    float inv = __int_as_float((127 - fb) << 23);
    float mq = rintf(m * fs) * inv;
    if (mq >= 2.0f) { s += 1; mq = 1.0f; }
    float y = mq * __int_as_float((127 + s) << 23);
    return copysignf(y, x);
}

__device__ __forceinline__ uint32_t pq2(float a, float b) {
    __nv_bfloat162 t = __floats2bfloat162_rn(posit_q(a), posit_q(b));
    return *reinterpret_cast<uint32_t*>(&t);
}

#define X4 ((NROWS * KDIM) / 4)            // 4194304
#define W4 ((NOUT * KDIM) / 4)             // 1048576

// One fused quant launch: x (float4), then w (float4), then bias (scalar)
__global__ void quant_all_kernel(const float* __restrict__ x,
                                 const float* __restrict__ w,
                                 const float* __restrict__ b) {
    int i = blockIdx.x * blockDim.x + threadIdx.x;
    if (i < X4) {
        float4 v = reinterpret_cast<const float4*>(x)[i];
        uint2 o; o.x = pq2(v.x, v.y); o.y = pq2(v.z, v.w);
        reinterpret_cast<uint2*>(g_xq)[i] = o;
    } else if (i < X4 + W4) {
        int j = i - X4;
        float4 v = reinterpret_cast<const float4*>(w)[j];
        uint2 o; o.x = pq2(v.x, v.y); o.y = pq2(v.z, v.w);
        reinterpret_cast<uint2*>(g_wq)[j] = o;
    } else if (i < X4 + W4 + NOUT) {
        int j = i - X4 - W4;
        g_bq[j] = posit_q(b[j]);
    }
}

// ---------------------------------------------------------------------------
// bf16 mma.sync GEMM: out = xq @ wq^T + bq  (M=8192, N=2048, K=2048)
// BM=128 x BN=128, BK=64, STAGES=3, 256 threads (8 warps, 2x4),
// warp tile 64x32, 2 CTAs/SM, ping-pong fragment pipeline in registers.
// ---------------------------------------------------------------------------
#define BM 128
#define BN 128
#define BK 64
#define STAGES 3
#define KITERS (KDIM / BK)                 // 32
#define A_BYTES (BM * 128)                 // 16 KB
#define B_BYTES (BN * 128)                 // 16 KB
#define STAGE_BYTES (A_BYTES + B_BYTES)    // 32 KB
#define SMEM_DYN (STAGES * STAGE_BYTES + 1024)

__device__ __forceinline__ uint32_t swz(uint32_t row, uint32_t byte) {
    return row * 128u + (byte ^ ((row & 7u) * 16u));
}

__device__ __forceinline__ uint32_t smem_u32(const void* p) {
    uint32_t a;
    asm("{ .reg .u64 t; cvta.to.shared.u64 t, %1; cvt.u32.u64 %0, t; }"
        : "=r"(a) : "l"(p));
    return a;
}

__device__ __forceinline__ void cp16(uint32_t dst, const void* src) {
    asm volatile("cp.async.cg.shared.global [%0], [%1], 16;"
                 :: "r"(dst), "l"(src) : "memory");
}

__device__ __forceinline__ void ldsm4(uint32_t& r0, uint32_t& r1,
                                      uint32_t& r2, uint32_t& r3, uint32_t a) {
    asm volatile("ldmatrix.sync.aligned.m8n8.x4.shared.b16 {%0,%1,%2,%3}, [%4];"
                 : "=r"(r0), "=r"(r1), "=r"(r2), "=r"(r3) : "r"(a));
}

__device__ __forceinline__ void mma16816(float* d, const uint32_t* a,
                                         uint32_t b0, uint32_t b1) {
    asm volatile(
        "mma.sync.aligned.m16n8k16.row.col.f32.bf16.bf16.f32 "
        "{%0,%1,%2,%3}, {%4,%5,%6,%7}, {%8,%9}, {%0,%1,%2,%3};"
        : "+f"(d[0]), "+f"(d[1]), "+f"(d[2]), "+f"(d[3])
        : "r"(a[0]), "r"(a[1]), "r"(a[2]), "r"(a[3]), "r"(b0), "r"(b1));
}

__global__ void __launch_bounds__(256, 2)
gemm_kernel(float* __restrict__ out) {
    extern __shared__ char smem_raw[];
    uint32_t sb = smem_u32(smem_raw);
    sb = (sb + 1023u) & ~1023u;

    const int tid  = threadIdx.x;
    const int wid  = tid >> 5, lane = tid & 31;
    const int wm   = wid & 1;        // 2 warps along M (64 rows each)
    const int wn   = wid >> 1;       // 4 warps along N (32 cols each)
    const int n0   = blockIdx.x * BN;
    const int m0   = blockIdx.y * BM;

    const char* agp = (const char*)g_xq + (size_t)(m0 + (tid >> 1)) * KDIM * 2
                      + (tid & 1) * 64;
    const char* bgp = (const char*)g_wq + (size_t)(n0 + (tid >> 1)) * KDIM * 2
                      + (tid & 1) * 64;

    auto load_stage = [&](int s, int it) {
        const uint32_t ab = sb + s * STAGE_BYTES;
        const uint32_t bb = ab + A_BYTES;
        const int koff = it * 128;                       // BK*2 bytes
        const uint32_t r  = tid >> 1;
        const uint32_t c0 = (tid & 1) * 64;
        #pragma unroll
        for (int c = 0; c < 4; c++)
            cp16(ab + swz(r, c0 + c * 16), agp + koff + c * 16);
        #pragma unroll
        for (int c = 0; c < 4; c++)
            cp16(bb + swz(r, c0 + c * 16), bgp + koff + c * 16);
    };

    #pragma unroll
    for (int s = 0; s < STAGES - 1; s++) {
        load_stage(s, s);
        asm volatile("cp.async.commit_group;" ::: "memory");
    }

    float acc[4][4][4];
    #pragma unroll
    for (int i = 0; i < 4; i++)
        #pragma unroll
        for (int j = 0; j < 4; j++)
            #pragma unroll
            for (int v = 0; v < 4; v++) acc[i][j][v] = 0.0f;

    const uint32_t a_row_lm  = wm * 64 + (lane & 15);         // + mt*16
    const uint32_t a_byte_lm = (lane >> 4) * 16;              // + kk*32
    const uint32_t b_row_lm  = wn * 32 + ((lane >> 4) * 8) + (lane & 7); // +p*16
    const uint32_t b_byte_lm = ((lane >> 3) & 1) * 16;        // + kk*32

    int s_rd = 0, s_wr = STAGES - 1;
    for (int it = 0; it < KITERS; ++it) {
        asm volatile("cp.async.wait_group %0;" :: "n"(STAGES - 2) : "memory");
        __syncthreads();

        const uint32_t ab = sb + s_rd * STAGE_BYTES;
        const uint32_t bb = ab + A_BYTES;
        if (++s_rd == STAGES) s_rd = 0;

        // Ping-pong fragment buffers
        uint32_t af[2][4], bf[2][8];
        // Stage-head preload: first A tile + first B pair (kk=0)
        ldsm4(af[0][0], af[0][1], af[0][2], af[0][3],
              ab + swz(a_row_lm, a_byte_lm));
        ldsm4(bf[0][0], bf[0][1], bf[0][2], bf[0][3],
              bb + swz(b_row_lm, b_byte_lm));
        ldsm4(bf[0][4], bf[0][5], bf[0][6], bf[0][7],
              bb + swz(b_row_lm + 16, b_byte_lm));

        // Issue next-stage gmem loads after the preload LDSMs
        if (it + STAGES - 1 < KITERS)
            load_stage(s_wr, it + STAGES - 1);
        asm volatile("cp.async.commit_group;" ::: "memory");
        if (++s_wr == STAGES) s_wr = 0;

        #pragma unroll
        for (int kk = 0; kk < 4; kk++) {
            const int bc = kk & 1;
            #pragma unroll
            for (int mt = 0; mt < 4; mt++) {
                const int g  = kk * 4 + mt;
                const int ac = g & 1, an = ac ^ 1;
                // Prefetch next A fragment (next mt, or next kk's mt=0)
                if (mt < 3)
                    ldsm4(af[an][0], af[an][1], af[an][2], af[an][3],
                          ab + swz(a_row_lm + (mt + 1) * 16,
                                   kk * 32 + a_byte_lm));
                else if (kk < 3)
                    ldsm4(af[an][0], af[an][1], af[an][2], af[an][3],
                          ab + swz(a_row_lm, (kk + 1) * 32 + a_byte_lm));
                // Prefetch next kk's B pair once per kk
                if (mt == 0 && kk < 3) {
                    const int bn_ = bc ^ 1;
                    ldsm4(bf[bn_][0], bf[bn_][1], bf[bn_][2], bf[bn_][3],
                          bb + swz(b_row_lm, (kk + 1) * 32 + b_byte_lm));
                    ldsm4(bf[bn_][4], bf[bn_][5], bf[bn_][6], bf[bn_][7],
                          bb + swz(b_row_lm + 16, (kk + 1) * 32 + b_byte_lm));
                }
                mma16816(acc[mt][0], af[ac], bf[bc][0], bf[bc][1]);
                mma16816(acc[mt][1], af[ac], bf[bc][2], bf[bc][3]);
                mma16816(acc[mt][2], af[ac], bf[bc][4], bf[bc][5]);
                mma16816(acc[mt][3], af[ac], bf[bc][6], bf[bc][7]);
            }
        }
    }

    // Epilogue: direct float2 stores + bias
    const int ncol = n0 + wn * 32 + (lane & 3) * 2;
    float2 bv[4];
    #pragma unroll
    for (int nt = 0; nt < 4; nt++)
        bv[nt] = *reinterpret_cast<const float2*>(&g_bq[ncol + nt * 8]);

    const int mrow = m0 + wm * 64 + (lane >> 2);
    #pragma unroll
    for (int mt = 0; mt < 4; mt++) {
        float* r0 = out + (size_t)(mrow + mt * 16) * NOUT;
        float* r1 = r0 + 8 * NOUT;
        #pragma unroll
        for (int nt = 0; nt < 4; nt++) {
            float2 lo = make_float2(acc[mt][nt][0] + bv[nt].x,
                                    acc[mt][nt][1] + bv[nt].y);
            float2 hi = make_float2(acc[mt][nt][2] + bv[nt].x,
                                    acc[mt][nt][3] + bv[nt].y);
            *reinterpret_cast<float2*>(r0 + ncol + nt * 8) = lo;
            *reinterpret_cast<float2*>(r1 + ncol + nt * 8) = hi;
        }
    }
}

// ---------------------------------------------------------------------------
extern "C" void kernel_launch(void* const* d_in, const int* in_sizes, int n_in,
                              void* d_out, int out_size) {
    const float* x = nullptr; const float* w = nullptr; const float* b = nullptr;
    for (int i = 0; i < n_in; i++) {
        if (in_sizes[i] == NROWS * KDIM)      x = (const float*)d_in[i];
        else if (in_sizes[i] == NOUT * KDIM)  w = (const float*)d_in[i];
        else if (in_sizes[i] == NOUT)         b = (const float*)d_in[i];
    }

    {
        int total = X4 + W4 + NOUT;
        quant_all_kernel<<<(total + 255) / 256, 256>>>(x, w, b);
    }

    cudaFuncSetAttribute(gemm_kernel,
                         cudaFuncAttributeMaxDynamicSharedMemorySize, SMEM_DYN);
    dim3 grid(NOUT / BN, NROWS / BM);   // (16, 64)
    gemm_kernel<<<grid, 256, SMEM_DYN>>>((float*)d_out);
}